// round 13
// baseline (speedup 1.0000x reference)
#include <cuda_runtime.h>
#include <cstdint>

#define ND 128
#define ED 64
#define HID 256
#define NMAX 100000
#define TM 64
#define NTHREADS 256

typedef unsigned long long ull;

__device__ __forceinline__ ull pack2(float lo, float hi) {
    ull r; asm("mov.b64 %0, {%1, %2};" : "=l"(r) : "f"(lo), "f"(hi)); return r;
}
__device__ __forceinline__ void fma2(ull &d, ull a, ull b) {
    asm("fma.rn.f32x2 %0, %1, %2, %0;" : "+l"(d) : "l"(a), "l"(b));
}
__device__ __forceinline__ ull add2(ull a, ull b) {
    ull r; asm("add.rn.f32x2 %0, %1, %2;" : "=l"(r) : "l"(a), "l"(b)); return r;
}
__device__ __forceinline__ float2 unpack2(ull v) {
    float2 f; asm("mov.b64 {%0, %1}, %2;" : "=f"(f.x), "=f"(f.y) : "l"(v)); return f;
}
__device__ __forceinline__ ull relu2(ull v) {
    float2 f = unpack2(v);
    return pack2(fmaxf(f.x, 0.f), fmaxf(f.y, 0.f));
}

// Per-node precomputed partials: Pa = x@W1a + b1, Pb = x@W1b
__device__ __align__(16) float g_Pa[(size_t)NMAX * HID];
__device__ __align__(16) float g_Pb[(size_t)NMAX * HID];

extern __shared__ float smem[];

// ============ Kernel 1: node precompute — LDG weights, zero barriers ===========
__global__ __launch_bounds__(NTHREADS, 2) void precompute_kernel(
    const float* __restrict__ x,
    const float* __restrict__ w1, const float* __restrict__ b1, int N)
{
    float* Xs = smem;              // [64][128] 32 KB, own-warp rows only

    const int tid = threadIdx.x;
    const int tx  = tid & 31;
    const int ty  = tid >> 5;
    const int r0  = ty * 8;
    const int m0  = blockIdx.x * TM;

    int node[8];
    #pragma unroll
    for (int r = 0; r < 8; r++) {
        node[r] = min(m0 + r0 + r, N - 1);
        ((float4*)(Xs + (r0 + r) * ND))[tx] =
            ((const float4*)(x + (size_t)node[r] * ND))[tx];
    }
    // no sync: each warp reads only its own Xs rows

    #pragma unroll
    for (int half = 0; half < 2; half++) {
        ull acc[8][4];
        if (half == 0) {
            ulonglong2 bvA = ((const ulonglong2*)b1)[tx];
            ulonglong2 bvB = ((const ulonglong2*)b1)[tx + 32];
            #pragma unroll
            for (int i = 0; i < 8; i++) {
                acc[i][0] = bvA.x; acc[i][1] = bvA.y;
                acc[i][2] = bvB.x; acc[i][3] = bvB.y;
            }
        } else {
            #pragma unroll
            for (int i = 0; i < 8; i++)
                #pragma unroll
                for (int j = 0; j < 4; j++) acc[i][j] = 0ull;
        }

        const float* wbase = w1 + (size_t)half * ND * HID;
        #pragma unroll 2
        for (int kk4 = 0; kk4 < ND; kk4 += 4) {
            float4 a4[8];
            #pragma unroll
            for (int i = 0; i < 8; i++)
                a4[i] = *(const float4*)(Xs + (r0 + i) * ND + kk4);
            #pragma unroll
            for (int kq = 0; kq < 4; kq++) {
                const ulonglong2* Br = (const ulonglong2*)(wbase + (kk4 + kq) * HID);
                ulonglong2 bA = Br[tx];        // cols 4tx..4tx+3   (LDG.128)
                ulonglong2 bB = Br[tx + 32];   // cols 128+4tx..
                #pragma unroll
                for (int i = 0; i < 8; i++) {
                    float a = (&a4[i].x)[kq];
                    ull aa = pack2(a, a);
                    fma2(acc[i][0], aa, bA.x);
                    fma2(acc[i][1], aa, bA.y);
                    fma2(acc[i][2], aa, bB.x);
                    fma2(acc[i][3], aa, bB.y);
                }
            }
        }

        float* P = half ? g_Pb : g_Pa;
        #pragma unroll
        for (int i = 0; i < 8; i++) {
            ulonglong2* dst = (ulonglong2*)(P + (size_t)node[i] * HID);
            dst[tx]      = make_ulonglong2(acc[i][0], acc[i][1]);
            dst[tx + 32] = make_ulonglong2(acc[i][2], acc[i][3]);
        }
    }
}

// ===================== Kernel 2: per-edge fused MLP + LN — zero barriers ========
// SMEM: Es [64][64] 16 KB | Hs [64][256] 64 KB  (both own-warp rows only)
#define EDGE_SMEM ((TM * ED + TM * HID) * 4)   // 81920 B -> 2 CTAs/SM

__global__ __launch_bounds__(NTHREADS, 2) void edge_kernel(
    const int* __restrict__ ei32,
    const float* __restrict__ edge_attr,
    const float* __restrict__ w1,       // rows [256,320) = W1c
    const float* __restrict__ w2, const float* __restrict__ b2,
    const float* __restrict__ ln_w, const float* __restrict__ ln_b,
    float* __restrict__ out, int E, int N)
{
    float* Es = smem;
    float* Hs = smem + TM * ED;

    const int tid = threadIdx.x;
    const int tx  = tid & 31;
    const int ty  = tid >> 5;
    const int r0  = ty * 8;
    const int e0  = blockIdx.x * TM;

    // int64/int32 detection
    unsigned oddbits = 0;
    #pragma unroll
    for (int k = 0; k < 16; k++) oddbits |= (unsigned)ei32[2 * k + 1];
    const int step = (oddbits == 0) ? 2 : 1;

    // per-row: ea -> Es (own warp rows); acc = Pa[dst] + Pb[src]  (LDG.128)
    ull acc[8][4];
    #pragma unroll
    for (int r = 0; r < 8; r++) {
        int e = min(e0 + r0 + r, E - 1);
        int ss = ei32[(size_t)step * e];
        int ds = ei32[(size_t)step * (E + e)];
        ss = min(max(ss, 0), N - 1);
        ds = min(max(ds, 0), N - 1);
        if (tx < 16)
            ((float4*)(Es + (r0 + r) * ED))[tx] =
                ((const float4*)(edge_attr + (size_t)e * ED))[tx];
        const ulonglong2* pa = (const ulonglong2*)(g_Pa + (size_t)ds * HID);
        const ulonglong2* pb = (const ulonglong2*)(g_Pb + (size_t)ss * HID);
        ulonglong2 a0 = pa[tx],      b0 = pb[tx];
        ulonglong2 a1 = pa[tx + 32], b1v = pb[tx + 32];
        acc[r][0] = add2(a0.x, b0.x);
        acc[r][1] = add2(a0.y, b0.y);
        acc[r][2] = add2(a1.x, b1v.x);
        acc[r][3] = add2(a1.y, b1v.y);
    }
    // no sync: Es rows are own-warp

    // -------- GEMM1 remainder: acc += ea @ W1c (K = 64), B via LDG.128 --------
    const float* w1c = w1 + (size_t)(2 * ND) * HID;
    #pragma unroll 4
    for (int kk4 = 0; kk4 < ED; kk4 += 4) {
        float4 a4[8];
        #pragma unroll
        for (int i = 0; i < 8; i++)
            a4[i] = *(const float4*)(Es + (r0 + i) * ED + kk4);
        #pragma unroll
        for (int kq = 0; kq < 4; kq++) {
            const ulonglong2* Br = (const ulonglong2*)(w1c + (kk4 + kq) * HID);
            ulonglong2 bA = Br[tx];
            ulonglong2 bB = Br[tx + 32];
            #pragma unroll
            for (int i = 0; i < 8; i++) {
                float a = (&a4[i].x)[kq];
                ull aa = pack2(a, a);
                fma2(acc[i][0], aa, bA.x);
                fma2(acc[i][1], aa, bA.y);
                fma2(acc[i][2], aa, bB.x);
                fma2(acc[i][3], aa, bB.y);
            }
        }
    }

    // h = relu(acc) -> Hs (own rows; STS.128)
    #pragma unroll
    for (int i = 0; i < 8; i++) {
        ulonglong2* hr = (ulonglong2*)(Hs + (r0 + i) * HID);
        hr[tx]      = make_ulonglong2(relu2(acc[i][0]), relu2(acc[i][1]));
        hr[tx + 32] = make_ulonglong2(relu2(acc[i][2]), relu2(acc[i][3]));
    }
    // no sync: GEMM2 A reads only own-warp Hs rows

    // -------- GEMM2: delta = h @ W2 (K = 256), B via LDG.64 --------
    ull acc2[8];
    #pragma unroll
    for (int i = 0; i < 8; i++) acc2[i] = 0ull;

    #pragma unroll 2
    for (int kk4 = 0; kk4 < HID; kk4 += 4) {
        float4 a4[8];
        #pragma unroll
        for (int i = 0; i < 8; i++)
            a4[i] = *(const float4*)(Hs + (r0 + i) * HID + kk4);
        #pragma unroll
        for (int kq = 0; kq < 4; kq++) {
            ull b = *((const ull*)(w2 + (size_t)(kk4 + kq) * ED) + tx);
            #pragma unroll
            for (int i = 0; i < 8; i++) {
                float a = (&a4[i].x)[kq];
                fma2(acc2[i], pack2(a, a), b);
            }
        }
    }

    // -------- Epilogue: residual + LayerNorm(64) + affine (cols {2tx,2tx+1}) ------
    float2 b2v = ((const float2*)b2)[tx];
    float2 lwv = ((const float2*)ln_w)[tx];
    float2 lbv = ((const float2*)ln_b)[tx];

    #pragma unroll
    for (int i = 0; i < 8; i++) {
        float2 d  = unpack2(acc2[i]);
        float2 ar = ((const float2*)(Es + (r0 + i) * ED))[tx];
        float v0 = ar.x + d.x + b2v.x;
        float v1 = ar.y + d.y + b2v.y;
        float s = v0 + v1;
        float q = v0 * v0 + v1 * v1;
        #pragma unroll
        for (int off = 16; off > 0; off >>= 1) {
            s += __shfl_xor_sync(0xffffffffu, s, off);
            q += __shfl_xor_sync(0xffffffffu, q, off);
        }
        float mean = s * 0.015625f;
        float var  = q * 0.015625f - mean * mean;
        float inv  = rsqrtf(var + 1e-5f);
        int e = e0 + r0 + i;
        if (e < E) {
            float2 o;
            o.x = (v0 - mean) * inv * lwv.x + lbv.x;
            o.y = (v1 - mean) * inv * lwv.y + lbv.y;
            ((float2*)(out + (size_t)e * ED))[tx] = o;
        }
    }
}

extern "C" void kernel_launch(void* const* d_in, const int* in_sizes, int n_in,
                              void* d_out, int out_size) {
    const float* x   = (const float*)d_in[0];
    const int*   ei  = (const int*)d_in[1];
    const float* ea  = (const float*)d_in[2];
    const float* w1  = (const float*)d_in[3];
    const float* b1  = (const float*)d_in[4];
    const float* w2  = (const float*)d_in[5];
    const float* b2  = (const float*)d_in[6];
    const float* lnw = (const float*)d_in[7];
    const float* lnb = (const float*)d_in[8];
    float* out = (float*)d_out;

    int E = in_sizes[1] / 2;
    int N = in_sizes[0] / ND;

    static int init_done = 0;
    int smem_pre = (TM * ND) * (int)sizeof(float);   // 32768
    if (!init_done) {
        cudaFuncSetAttribute(precompute_kernel,
                             cudaFuncAttributeMaxDynamicSharedMemorySize, smem_pre);
        cudaFuncSetAttribute(edge_kernel,
                             cudaFuncAttributeMaxDynamicSharedMemorySize, EDGE_SMEM);
        init_done = 1;
    }

    int pgrid = (N + TM - 1) / TM;
    precompute_kernel<<<pgrid, NTHREADS, smem_pre>>>(x, w1, b1, N);

    int egrid = (E + TM - 1) / TM;
    edge_kernel<<<egrid, NTHREADS, EDGE_SMEM>>>(
        ei, ea, w1, w2, b2, lnw, lnb, out, E, N);
}

// round 14
// speedup vs baseline: 1.1668x; 1.1668x over previous
#include <cuda_runtime.h>
#include <cuda_bf16.h>
#include <cstdint>

#define ND 128
#define ED 64
#define HID 256
#define NMAX 100000
#define TM 64
#define NTHREADS 256

typedef unsigned long long ull;

__device__ __forceinline__ ull pack2(float lo, float hi) {
    ull r; asm("mov.b64 %0, {%1, %2};" : "=l"(r) : "f"(lo), "f"(hi)); return r;
}
__device__ __forceinline__ void fma2(ull &d, ull a, ull b) {
    asm("fma.rn.f32x2 %0, %1, %2, %0;" : "+l"(d) : "l"(a), "l"(b));
}
__device__ __forceinline__ ull add2(ull a, ull b) {
    ull r; asm("add.rn.f32x2 %0, %1, %2;" : "=l"(r) : "l"(a), "l"(b)); return r;
}
__device__ __forceinline__ float2 unpack2(ull v) {
    float2 f; asm("mov.b64 {%0, %1}, %2;" : "=f"(f.x), "=f"(f.y) : "l"(v)); return f;
}
__device__ __forceinline__ uint32_t smem_u32(const void* p) {
    uint32_t a;
    asm("{ .reg .u64 t; cvta.to.shared.u64 t, %1; cvt.u32.u64 %0, t; }" : "=r"(a) : "l"(p));
    return a;
}
__device__ __forceinline__ void ldsm4(uint32_t* r, uint32_t addr) {
    asm volatile("ldmatrix.sync.aligned.m8n8.x4.shared.b16 {%0,%1,%2,%3}, [%4];"
                 : "=r"(r[0]), "=r"(r[1]), "=r"(r[2]), "=r"(r[3]) : "r"(addr));
}
__device__ __forceinline__ void ldsm4t(uint32_t* r, uint32_t addr) {
    asm volatile("ldmatrix.sync.aligned.m8n8.x4.trans.shared.b16 {%0,%1,%2,%3}, [%4];"
                 : "=r"(r[0]), "=r"(r[1]), "=r"(r[2]), "=r"(r[3]) : "r"(addr));
}
__device__ __forceinline__ void mma16816(float* c, const uint32_t* a,
                                         uint32_t b0, uint32_t b1) {
    asm volatile(
        "mma.sync.aligned.m16n8k16.row.col.f32.bf16.bf16.f32 "
        "{%0,%1,%2,%3}, {%4,%5,%6,%7}, {%8,%9}, {%0,%1,%2,%3};"
        : "+f"(c[0]), "+f"(c[1]), "+f"(c[2]), "+f"(c[3])
        : "r"(a[0]), "r"(a[1]), "r"(a[2]), "r"(a[3]), "r"(b0), "r"(b1));
}
__device__ __forceinline__ uint32_t packbf(float v0, float v1) {
    uint32_t r; asm("cvt.rn.bf16x2.f32 %0, %1, %2;" : "=r"(r) : "f"(v1), "f"(v0));
    return r;
}
__device__ __forceinline__ void split_bf(float v, float& hf, float& lf) {
    __nv_bfloat16 h = __float2bfloat16(v);
    hf = __bfloat162float(h);
    lf = v - hf;
}

// device-global scratch
__device__ __align__(16) float g_Pa[(size_t)NMAX * HID];   // x@W1a + b1
__device__ __align__(16) float g_Pb[(size_t)NMAX * HID];   // x@W1b
// W2 bf16 image: 4 k-chunks, each [hi|lo][64][72]  (verified R7 layout)
__device__ __align__(16) __nv_bfloat16 g_W2img[4][2 * 64 * 72];

// ---- edge-kernel SMEM byte offsets ----
#define ES_OFF   0                        // fp32 ea [64][64] = 16384
#define HS_HI    16384                    // h bf16 hi [64 rows][528 B] = 33792
#define HS_LO    50176                    // h bf16 lo
#define CB_HI    83968                    // W2 chunk hi [64][72] bf16 = 9216
#define CB_LO    93184                    // W2 chunk lo
#define DB_OFF   83968                    // delta fp32 [64][68] = 17408 (reuses CB)
#define EDGE_SMEM 102400                  // -> 2 CTAs/SM

extern __shared__ float smem[];

// ===================== Prep: W2 -> bf16 hi/lo image ============================
__global__ void prep_w2(const float* __restrict__ w2) {
    int j = blockIdx.x * blockDim.x + threadIdx.x;
    if (j < HID * ED) {
        int k = j / ED, n = j % ED;
        float v = w2[(size_t)k * ED + n];
        float hf, lf; split_bf(v, hf, lf);
        int ch = k >> 6, kk = k & 63;
        g_W2img[ch][kk * 72 + n]           = __float2bfloat16(hf);
        g_W2img[ch][64 * 72 + kk * 72 + n] = __float2bfloat16(lf);
    }
}

// ============ Kernel 1: node precompute (R9 merged version, proven) ============
__global__ __launch_bounds__(NTHREADS, 2) void precompute_kernel(
    const float* __restrict__ x,
    const float* __restrict__ w1, const float* __restrict__ b1, int N)
{
    float* Xs = smem;              // [64][128]
    float* Bs = smem + TM * ND;    // [64][256]

    const int tid = threadIdx.x;
    const int tx  = tid & 31;
    const int ty  = tid >> 5;
    const int r0  = ty * 8;
    const int m0  = blockIdx.x * TM;

    int node[8];
    #pragma unroll
    for (int r = 0; r < 8; r++) {
        node[r] = min(m0 + r0 + r, N - 1);
        ((float4*)(Xs + (r0 + r) * ND))[tx] =
            ((const float4*)(x + (size_t)node[r] * ND))[tx];
    }

    for (int half = 0; half < 2; half++) {
        ull acc[8][4];
        if (half == 0) {
            ull bv[4];
            #pragma unroll
            for (int j = 0; j < 4; j++) {
                float2 b = ((const float2*)b1)[tx + 32 * j];
                bv[j] = pack2(b.x, b.y);
            }
            #pragma unroll
            for (int i = 0; i < 8; i++)
                #pragma unroll
                for (int j = 0; j < 4; j++) acc[i][j] = bv[j];
        } else {
            #pragma unroll
            for (int i = 0; i < 8; i++)
                #pragma unroll
                for (int j = 0; j < 4; j++) acc[i][j] = 0ull;
        }

        for (int kt = 0; kt < ND; kt += 64) {
            __syncthreads();
            const float4* wf4 = (const float4*)(w1 + (size_t)(half * ND + kt) * HID);
            #pragma unroll
            for (int it = 0; it < 16; it++) {
                int q = tid + it * NTHREADS;
                ((float4*)Bs)[q] = wf4[q];
            }
            __syncthreads();
            #pragma unroll 4
            for (int kk4 = 0; kk4 < 64; kk4 += 4) {
                float4 a4[8];
                #pragma unroll
                for (int i = 0; i < 8; i++)
                    a4[i] = *(const float4*)(Xs + (r0 + i) * ND + kt + kk4);
                #pragma unroll
                for (int kq = 0; kq < 4; kq++) {
                    const ull* Br = (const ull*)(Bs + (kk4 + kq) * HID) + tx;
                    ull b0 = Br[0], b1r = Br[32], b2r = Br[64], b3r = Br[96];
                    #pragma unroll
                    for (int i = 0; i < 8; i++) {
                        float a = (&a4[i].x)[kq];
                        ull aa = pack2(a, a);
                        fma2(acc[i][0], aa, b0);
                        fma2(acc[i][1], aa, b1r);
                        fma2(acc[i][2], aa, b2r);
                        fma2(acc[i][3], aa, b3r);
                    }
                }
            }
        }

        float* P = half ? g_Pb : g_Pa;
        #pragma unroll
        for (int i = 0; i < 8; i++) {
            float2* dst = (float2*)(P + (size_t)node[i] * HID);
            #pragma unroll
            for (int j = 0; j < 4; j++)
                dst[tx + 32 * j] = unpack2(acc[i][j]);
        }
    }
}

// ========== Kernel 2: edge — GEMM1 on FFMA2, GEMM2 on HMMA bf16x3 ==============
__global__ __launch_bounds__(NTHREADS, 2) void edge_kernel(
    const int* __restrict__ ei32,
    const float* __restrict__ edge_attr,
    const float* __restrict__ w1,       // rows [256,320) = W1c (read via LDG)
    const float* __restrict__ b2,
    const float* __restrict__ ln_w, const float* __restrict__ ln_b,
    float* __restrict__ out, int E, int N)
{
    unsigned char* sm = (unsigned char*)smem;
    const uint32_t sb = smem_u32(sm);
    float* Es = (float*)(sm + ES_OFF);

    const int tid  = threadIdx.x;
    const int tx   = tid & 31;
    const int ty   = tid >> 5;         // warp 0..7
    const int r0   = ty * 8;
    const int lane = tx;
    const int mg   = ty & 3;           // GEMM2 row group (16 rows)
    const int ng   = ty >> 2;          // GEMM2 col group (32 cols)
    const int e0   = blockIdx.x * TM;

    // int64/int32 detection
    unsigned oddbits = 0;
    #pragma unroll
    for (int k = 0; k < 16; k++) oddbits |= (unsigned)ei32[2 * k + 1];
    const int step = (oddbits == 0) ? 2 : 1;

    // ---- gather: ea -> Es (own rows); acc = Pa[dst] + Pb[src]  (LDG.128) ----
    ull acc[8][4];
    #pragma unroll
    for (int r = 0; r < 8; r++) {
        int e = min(e0 + r0 + r, E - 1);
        int ss = ei32[(size_t)step * e];
        int ds = ei32[(size_t)step * (E + e)];
        ss = min(max(ss, 0), N - 1);
        ds = min(max(ds, 0), N - 1);
        if (tx < 16)
            ((float4*)(Es + (r0 + r) * ED))[tx] =
                ((const float4*)(edge_attr + (size_t)e * ED))[tx];
        const ulonglong2* pa = (const ulonglong2*)(g_Pa + (size_t)ds * HID);
        const ulonglong2* pb = (const ulonglong2*)(g_Pb + (size_t)ss * HID);
        ulonglong2 a0 = pa[tx],      b0 = pb[tx];
        ulonglong2 a1 = pa[tx + 32], b1v = pb[tx + 32];
        acc[r][0] = add2(a0.x, b0.x);    // cols 4tx..4tx+1
        acc[r][1] = add2(a0.y, b0.y);    // cols 4tx+2..4tx+3
        acc[r][2] = add2(a1.x, b1v.x);   // cols 128+4tx..+1
        acc[r][3] = add2(a1.y, b1v.y);   // cols 128+4tx+2..+3
    }
    __syncwarp();

    // ---- GEMM1 remainder: acc += ea @ W1c (K=64), B via LDG.128 ----
    const float* w1c = w1 + (size_t)(2 * ND) * HID;
    #pragma unroll 4
    for (int kk4 = 0; kk4 < ED; kk4 += 4) {
        float4 a4[8];
        #pragma unroll
        for (int i = 0; i < 8; i++)
            a4[i] = *(const float4*)(Es + (r0 + i) * ED + kk4);
        #pragma unroll
        for (int kq = 0; kq < 4; kq++) {
            const ulonglong2* Br = (const ulonglong2*)(w1c + (kk4 + kq) * HID);
            ulonglong2 bA = Br[tx];
            ulonglong2 bB = Br[tx + 32];
            #pragma unroll
            for (int i = 0; i < 8; i++) {
                float a = (&a4[i].x)[kq];
                ull aa = pack2(a, a);
                fma2(acc[i][0], aa, bA.x);
                fma2(acc[i][1], aa, bA.y);
                fma2(acc[i][2], aa, bB.x);
                fma2(acc[i][3], aa, bB.y);
            }
        }
    }

    // ---- h = relu(acc) -> bf16 hi/lo tiles (row stride 528 B) ----
    #pragma unroll
    for (int i = 0; i < 8; i++) {
        unsigned rbase = (r0 + i) * 528;
        #pragma unroll
        for (int j = 0; j < 4; j++) {
            float2 v = unpack2(acc[i][j]);
            v.x = fmaxf(v.x, 0.f);
            v.y = fmaxf(v.y, 0.f);
            float h0, l0, h1, l1;
            split_bf(v.x, h0, l0);
            split_bf(v.y, h1, l1);
            // cols: j<2 -> 4tx+2j ; j>=2 -> 128+4tx+2(j-2); byte off = col*2
            unsigned cb = (j < 2) ? (8 * tx + 4 * j) : (256 + 8 * tx + 4 * (j - 2));
            *(uint32_t*)(sm + HS_HI + rbase + cb) = packbf(h0, h1);
            *(uint32_t*)(sm + HS_LO + rbase + cb) = packbf(l0, l1);
        }
    }
    __syncthreads();   // h visible to all warps

    // ---- GEMM2: delta = h @ W2  (HMMA bf16x3; warp = 16 rows x 32 cols) ----
    float c2[4][4];
    #pragma unroll
    for (int j = 0; j < 4; j++)
        #pragma unroll
        for (int q = 0; q < 4; q++) c2[j][q] = 0.f;

    for (int ch = 0; ch < 4; ch++) {
        if (ch > 0) __syncthreads();   // prev chunk reads done
        {
            const float4* src = (const float4*)g_W2img[ch];
            float4* dst = (float4*)(sm + CB_HI);
            #pragma unroll
            for (int q = 0; q < 5; q++) {
                int idx = tid + q * NTHREADS;   // 1152 float4 (hi+lo)
                if (idx < 1152) dst[idx] = src[idx];
            }
        }
        __syncthreads();
        #pragma unroll
        for (int k16 = 0; k16 < 4; k16++) {
            uint32_t aAddr = sb + HS_HI + (16 * mg + (lane & 15)) * 528
                           + (64 * ch + 16 * k16) * 2 + (lane >> 4) * 16;
            uint32_t ah[4], al[4];
            ldsm4(ah, aAddr);
            ldsm4(al, aAddr + (HS_LO - HS_HI));
            #pragma unroll
            for (int nt = 0; nt < 2; nt++) {
                uint32_t bAddr = sb + CB_HI + (k16 * 16 + (lane & 15)) * 144
                               + (32 * ng + 16 * nt) * 2 + (lane >> 4) * 16;
                uint32_t bh[4], bl[4];
                ldsm4t(bh, bAddr);
                ldsm4t(bl, bAddr + (CB_LO - CB_HI));
                mma16816(c2[2*nt],   ah, bh[0], bh[1]);
                mma16816(c2[2*nt],   al, bh[0], bh[1]);
                mma16816(c2[2*nt],   ah, bl[0], bl[1]);
                mma16816(c2[2*nt+1], ah, bh[2], bh[3]);
                mma16816(c2[2*nt+1], al, bh[2], bh[3]);
                mma16816(c2[2*nt+1], ah, bl[2], bl[3]);
            }
        }
    }
    __syncthreads();   // all CB reads done; CB region becomes delta buffer

    // ---- stage delta into fp32 Dbuf [64][68] ----
    {
        float* Db = (float*)(sm + DB_OFF);
        const int rlo = 16 * mg + (lane >> 2);
        const int rhi = rlo + 8;
        const int cq2 = 2 * (lane & 3);
        #pragma unroll
        for (int j = 0; j < 4; j++) {
            int col = 32 * ng + 8 * j + cq2;
            *(float2*)(Db + rlo * 68 + col) = make_float2(c2[j][0], c2[j][1]);
            *(float2*)(Db + rhi * 68 + col) = make_float2(c2[j][2], c2[j][3]);
        }
    }
    __syncthreads();

    // ---- Epilogue: residual + LayerNorm(64) + affine (cols {2tx,2tx+1}) ----
    const float* Db = (const float*)(sm + DB_OFF);
    float2 b2v = ((const float2*)b2)[tx];
    float2 lwv = ((const float2*)ln_w)[tx];
    float2 lbv = ((const float2*)ln_b)[tx];

    #pragma unroll
    for (int i = 0; i < 8; i++) {
        int r = r0 + i;
        float2 d  = *(const float2*)(Db + r * 68 + 2 * tx);
        float2 ar = ((const float2*)(Es + r * ED))[tx];
        float v0 = ar.x + d.x + b2v.x;
        float v1 = ar.y + d.y + b2v.y;
        float s = v0 + v1;
        float q = v0 * v0 + v1 * v1;
        #pragma unroll
        for (int off = 16; off > 0; off >>= 1) {
            s += __shfl_xor_sync(0xffffffffu, s, off);
            q += __shfl_xor_sync(0xffffffffu, q, off);
        }
        float mean = s * 0.015625f;
        float var  = q * 0.015625f - mean * mean;
        float inv  = rsqrtf(var + 1e-5f);
        int e = e0 + r;
        if (e < E) {
            float2 o;
            o.x = (v0 - mean) * inv * lwv.x + lbv.x;
            o.y = (v1 - mean) * inv * lwv.y + lbv.y;
            ((float2*)(out + (size_t)e * ED))[tx] = o;
        }
    }
}

extern "C" void kernel_launch(void* const* d_in, const int* in_sizes, int n_in,
                              void* d_out, int out_size) {
    const float* x   = (const float*)d_in[0];
    const int*   ei  = (const int*)d_in[1];
    const float* ea  = (const float*)d_in[2];
    const float* w1  = (const float*)d_in[3];
    const float* b1  = (const float*)d_in[4];
    const float* w2  = (const float*)d_in[5];
    const float* b2  = (const float*)d_in[6];
    const float* lnw = (const float*)d_in[7];
    const float* lnb = (const float*)d_in[8];
    float* out = (float*)d_out;

    int E = in_sizes[1] / 2;
    int N = in_sizes[0] / ND;

    static int init_done = 0;
    int smem_pre = (TM * ND + TM * HID) * (int)sizeof(float);   // 98304
    if (!init_done) {
        cudaFuncSetAttribute(precompute_kernel,
                             cudaFuncAttributeMaxDynamicSharedMemorySize, smem_pre);
        cudaFuncSetAttribute(edge_kernel,
                             cudaFuncAttributeMaxDynamicSharedMemorySize, EDGE_SMEM);
        init_done = 1;
    }

    prep_w2<<<(HID * ED + 255) / 256, 256>>>(w2);

    int pgrid = (N + TM - 1) / TM;
    precompute_kernel<<<pgrid, NTHREADS, smem_pre>>>(x, w1, b1, N);

    int egrid = (E + TM - 1) / TM;
    edge_kernel<<<egrid, NTHREADS, EDGE_SMEM>>>(
        ei, ea, w1, b2, lnw, lnb, out, E, N);
}